// round 2
// baseline (speedup 1.0000x reference)
#include <cuda_runtime.h>

#define B_ 64
#define T_ 512
#define E_ 512
#define H_ 512
#define O_ 512
#define BH_ (B_ * H_)
#define GREC 128

// Scratch (device globals — no runtime allocation allowed)
__device__ float g_A[(size_t)T_ * B_ * H_];          // [t][b][j]  x@W1x + b1
__device__ float g_Hall[(size_t)(T_ + 1) * B_ * H_]; // [t][b][k]  hidden history
__device__ unsigned int g_cnt[T_];                   // per-step barrier counters

// ---------------------------------------------------------------------------
// Init: zero step counters and h_0 (every replay — determinism)
// ---------------------------------------------------------------------------
__global__ void init_kernel() {
    int i = blockIdx.x * blockDim.x + threadIdx.x;
    if (i < T_) g_cnt[i] = 0u;
    if (i < BH_) g_Hall[i] = 0.0f;
}

// ---------------------------------------------------------------------------
// Pre-GEMM: A[t][b][j] = sum_e x[b,t,e] * W1[e][j] + b1[j]
// M = B*T (row m = b*T + t), N = H, K = E. 64x64 tile, BK=16, 4x4 microtile.
// ---------------------------------------------------------------------------
__global__ __launch_bounds__(256) void gemm_pre_kernel(
    const float* __restrict__ X, const float* __restrict__ W1,
    const float* __restrict__ b1) {
    __shared__ __align__(16) float As[16 * 64]; // [k][m]
    __shared__ __align__(16) float Bs[16 * 64]; // [k][n]
    const int tid = threadIdx.x;
    const int m0 = blockIdx.y * 64;
    const int n0 = blockIdx.x * 64;
    const int tx = tid & 15;
    const int ty = tid >> 4;
    const int a_m = tid >> 2;
    const int a_k = (tid & 3) * 4;
    const int b_k = tid >> 4;
    const int b_n = (tid & 15) * 4;

    float acc[4][4];
#pragma unroll
    for (int i = 0; i < 4; i++)
#pragma unroll
        for (int j = 0; j < 4; j++) acc[i][j] = 0.0f;

    for (int k0 = 0; k0 < E_; k0 += 16) {
        float4 av = *(const float4*)&X[(m0 + a_m) * E_ + k0 + a_k];
        float4 bv = *(const float4*)&W1[(k0 + b_k) * H_ + n0 + b_n];
        __syncthreads();
        As[(a_k + 0) * 64 + a_m] = av.x;
        As[(a_k + 1) * 64 + a_m] = av.y;
        As[(a_k + 2) * 64 + a_m] = av.z;
        As[(a_k + 3) * 64 + a_m] = av.w;
        *(float4*)&Bs[b_k * 64 + b_n] = bv;
        __syncthreads();
#pragma unroll
        for (int kk = 0; kk < 16; kk++) {
            float4 ra = *(const float4*)&As[kk * 64 + ty * 4];
            float4 rb = *(const float4*)&Bs[kk * 64 + tx * 4];
            acc[0][0] += ra.x * rb.x; acc[0][1] += ra.x * rb.y;
            acc[0][2] += ra.x * rb.z; acc[0][3] += ra.x * rb.w;
            acc[1][0] += ra.y * rb.x; acc[1][1] += ra.y * rb.y;
            acc[1][2] += ra.y * rb.z; acc[1][3] += ra.y * rb.w;
            acc[2][0] += ra.z * rb.x; acc[2][1] += ra.z * rb.y;
            acc[2][2] += ra.z * rb.z; acc[2][3] += ra.z * rb.w;
            acc[3][0] += ra.w * rb.x; acc[3][1] += ra.w * rb.y;
            acc[3][2] += ra.w * rb.z; acc[3][3] += ra.w * rb.w;
        }
    }

    const int jbase = n0 + tx * 4;
    float4 bias = *(const float4*)&b1[jbase];
#pragma unroll
    for (int i = 0; i < 4; i++) {
        int m = m0 + ty * 4 + i;
        int bb = m >> 9;   // m / T
        int tt = m & 511;  // m % T
        float4 o;
        o.x = acc[i][0] + bias.x;
        o.y = acc[i][1] + bias.y;
        o.z = acc[i][2] + bias.z;
        o.w = acc[i][3] + bias.w;
        *(float4*)&g_A[tt * BH_ + bb * H_ + jbase] = o;
    }
}

// ---------------------------------------------------------------------------
// Persistent recurrence: 128 CTAs, CTA owns 4 j-columns (W1h slice in SMEM
// for all steps). Per step: stage h_t in 128-k chunks (register prefetch),
// compute h_{t+1}[b][j] = sigmoid(A[t][b][j] + h_t[b][:] . W1h[:,j]),
// then a grid barrier on monotone per-step counters.
// ---------------------------------------------------------------------------
__global__ __launch_bounds__(256, 1) void recurrence_kernel(
    const float* __restrict__ W1, float* __restrict__ hid_out) {
    __shared__ __align__(16) float Ws[4 * 512];   // [jj][k]
    __shared__ __align__(16) float sh[64 * 132];  // h chunk [b][kk], pitch 132

    const int tid = threadIdx.x;
    const int j0 = blockIdx.x * 4;

    // Load W1h slice once: Ws[jj][k] = W1[(E+k)][j0+jj]
    for (int idx = tid; idx < 4 * 512; idx += 256) {
        int jj = idx >> 9;
        int k = idx & 511;
        Ws[jj * 512 + k] = W1[(E_ + k) * H_ + j0 + jj];
    }

    const int b = tid & 63;
    const int jj = tid >> 6;
    const int j = j0 + jj;

    int lb[8], lk[8];
#pragma unroll
    for (int i = 0; i < 8; i++) {
        int f4 = tid + i * 256;   // 0..2047 float4 slots of a 64x128 chunk
        lb[i] = f4 >> 5;          // row b
        lk[i] = (f4 & 31) * 4;    // col within chunk
    }
    __syncthreads();

    for (int t = 0; t < T_; t++) {
        const float* hprev = g_Hall + t * BH_;
        float acc0 = 0.f, acc1 = 0.f, acc2 = 0.f, acc3 = 0.f;

        float4 pf[8];
#pragma unroll
        for (int i = 0; i < 8; i++)
            pf[i] = *(const float4*)&hprev[lb[i] * H_ + lk[i]];

        for (int k0 = 0; k0 < H_; k0 += 128) {
            __syncthreads();
#pragma unroll
            for (int i = 0; i < 8; i++) {
                float* d = &sh[lb[i] * 132 + lk[i]];
                d[0] = pf[i].x; d[1] = pf[i].y; d[2] = pf[i].z; d[3] = pf[i].w;
            }
            __syncthreads();
            if (k0 + 128 < H_) {
#pragma unroll
                for (int i = 0; i < 8; i++)
                    pf[i] = *(const float4*)&hprev[lb[i] * H_ + (k0 + 128) + lk[i]];
            }
            const float* hrow = &sh[b * 132];
            const float* wrow = &Ws[jj * 512 + k0];
#pragma unroll
            for (int kk = 0; kk < 128; kk += 4) {
                float4 hv = *(const float4*)&hrow[kk];
                float4 wv = *(const float4*)&wrow[kk];
                acc0 += hv.x * wv.x;
                acc1 += hv.y * wv.y;
                acc2 += hv.z * wv.z;
                acc3 += hv.w * wv.w;
            }
        }

        float a = g_A[t * BH_ + b * H_ + j] + ((acc0 + acc1) + (acc2 + acc3));
        float hnew = 1.0f / (1.0f + __expf(-a));
        g_Hall[(t + 1) * BH_ + b * H_ + j] = hnew;
        if (hid_out != nullptr && t == T_ - 1) hid_out[b * H_ + j] = hnew;

        // grid barrier for step t
        __threadfence();   // release stores + CCTL.IVALL (L1 invalidate)
        __syncthreads();
        if (tid == 0) {
            atomicAdd(&g_cnt[t], 1u);
            while (*((volatile unsigned int*)&g_cnt[t]) < (unsigned)GREC) {}
        }
        __syncthreads();
    }
}

// ---------------------------------------------------------------------------
// Post-GEMM: out[b,t,j] = b2[j] + x[b,t,:]@W2x[:,j] + h_t[b,:]@W2h[:,j]
// K = 1024 (first 512 from X, last 512 from g_Hall). Output row m = b*T+t
// matches d_out layout [B,T,O] directly.
// ---------------------------------------------------------------------------
__global__ __launch_bounds__(256) void gemm_post_kernel(
    const float* __restrict__ X, const float* __restrict__ W2,
    const float* __restrict__ b2, float* __restrict__ out) {
    __shared__ __align__(16) float As[16 * 64];
    __shared__ __align__(16) float Bs[16 * 64];
    const int tid = threadIdx.x;
    const int m0 = blockIdx.y * 64;
    const int n0 = blockIdx.x * 64;
    const int tx = tid & 15;
    const int ty = tid >> 4;
    const int a_m = tid >> 2;
    const int a_k = (tid & 3) * 4;
    const int b_k = tid >> 4;
    const int b_n = (tid & 15) * 4;

    const int m_ld = m0 + a_m;
    const int tt_ld = m_ld & 511;
    const int bb_ld = m_ld >> 9;

    float acc[4][4];
#pragma unroll
    for (int i = 0; i < 4; i++)
#pragma unroll
        for (int j = 0; j < 4; j++) acc[i][j] = 0.0f;

    for (int k0 = 0; k0 < E_ + H_; k0 += 16) {
        float4 av;
        if (k0 < E_) {
            av = *(const float4*)&X[m_ld * E_ + k0 + a_k];
        } else {
            av = *(const float4*)&g_Hall[tt_ld * BH_ + bb_ld * H_ + (k0 - E_) + a_k];
        }
        float4 bv = *(const float4*)&W2[(k0 + b_k) * O_ + n0 + b_n];
        __syncthreads();
        As[(a_k + 0) * 64 + a_m] = av.x;
        As[(a_k + 1) * 64 + a_m] = av.y;
        As[(a_k + 2) * 64 + a_m] = av.z;
        As[(a_k + 3) * 64 + a_m] = av.w;
        *(float4*)&Bs[b_k * 64 + b_n] = bv;
        __syncthreads();
#pragma unroll
        for (int kk = 0; kk < 16; kk++) {
            float4 ra = *(const float4*)&As[kk * 64 + ty * 4];
            float4 rb = *(const float4*)&Bs[kk * 64 + tx * 4];
            acc[0][0] += ra.x * rb.x; acc[0][1] += ra.x * rb.y;
            acc[0][2] += ra.x * rb.z; acc[0][3] += ra.x * rb.w;
            acc[1][0] += ra.y * rb.x; acc[1][1] += ra.y * rb.y;
            acc[1][2] += ra.y * rb.z; acc[1][3] += ra.y * rb.w;
            acc[2][0] += ra.z * rb.x; acc[2][1] += ra.z * rb.y;
            acc[2][2] += ra.z * rb.z; acc[2][3] += ra.z * rb.w;
            acc[3][0] += ra.w * rb.x; acc[3][1] += ra.w * rb.y;
            acc[3][2] += ra.w * rb.z; acc[3][3] += ra.w * rb.w;
        }
    }

    const int jbase = n0 + tx * 4;
    float4 bias = *(const float4*)&b2[jbase];
#pragma unroll
    for (int i = 0; i < 4; i++) {
        int m = m0 + ty * 4 + i;
        float4 o;
        o.x = acc[i][0] + bias.x;
        o.y = acc[i][1] + bias.y;
        o.z = acc[i][2] + bias.z;
        o.w = acc[i][3] + bias.w;
        *(float4*)&out[m * O_ + jbase] = o;
    }
}

// ---------------------------------------------------------------------------
extern "C" void kernel_launch(void* const* d_in, const int* in_sizes, int n_in,
                              void* d_out, int out_size) {
    const float* x = (const float*)d_in[0];
    const float* W1 = (const float*)d_in[1];
    const float* b1 = (const float*)d_in[2];
    const float* W2 = (const float*)d_in[3];
    const float* b2 = (const float*)d_in[4];
    float* out = (float*)d_out;

    float* hid_out = nullptr;
    if (out_size >= B_ * T_ * O_ + B_ * H_)
        hid_out = out + (size_t)B_ * T_ * O_;

    init_kernel<<<128, 256>>>();
    gemm_pre_kernel<<<dim3(H_ / 64, (B_ * T_) / 64), 256>>>(x, W1, b1);
    recurrence_kernel<<<GREC, 256>>>(W1, hid_out);
    gemm_post_kernel<<<dim3(O_ / 64, (B_ * T_) / 64), 256>>>(x, W2, b2, out);
}

// round 3
// speedup vs baseline: 1.0005x; 1.0005x over previous
#include <cuda_runtime.h>

#define B_ 64
#define T_ 512
#define E_ 512
#define H_ 512
#define O_ 512
#define BH_ (B_ * H_)
#define GREC 128

// Scratch (device globals — no runtime allocation allowed)
__device__ float g_A[(size_t)T_ * B_ * H_];          // [t][b][j]  x@W1x + b1
__device__ float g_Hall[(size_t)(T_ + 1) * B_ * H_]; // [t][b][k]  hidden history
__device__ unsigned int g_cnt[T_];                   // per-step barrier counters

// ---------------------------------------------------------------------------
// Init: zero step counters and h_0 (every replay — determinism)
// ---------------------------------------------------------------------------
__global__ void init_kernel() {
    int i = blockIdx.x * blockDim.x + threadIdx.x;
    if (i < T_) g_cnt[i] = 0u;
    if (i < BH_) g_Hall[i] = 0.0f;
}

// ---------------------------------------------------------------------------
// Pre-GEMM: A[t][b][j] = sum_e x[b,t,e] * W1[e][j] + b1[j]
// M = B*T (row m = b*T + t), N = H, K = E. 64x64 tile, BK=16, 4x4 microtile.
// ---------------------------------------------------------------------------
__global__ __launch_bounds__(256) void gemm_pre_kernel(
    const float* __restrict__ X, const float* __restrict__ W1,
    const float* __restrict__ b1) {
    __shared__ __align__(16) float As[16 * 64]; // [k][m]
    __shared__ __align__(16) float Bs[16 * 64]; // [k][n]
    const int tid = threadIdx.x;
    const int m0 = blockIdx.y * 64;
    const int n0 = blockIdx.x * 64;
    const int tx = tid & 15;
    const int ty = tid >> 4;
    const int a_m = tid >> 2;
    const int a_k = (tid & 3) * 4;
    const int b_k = tid >> 4;
    const int b_n = (tid & 15) * 4;

    float acc[4][4];
#pragma unroll
    for (int i = 0; i < 4; i++)
#pragma unroll
        for (int j = 0; j < 4; j++) acc[i][j] = 0.0f;

    for (int k0 = 0; k0 < E_; k0 += 16) {
        float4 av = *(const float4*)&X[(m0 + a_m) * E_ + k0 + a_k];
        float4 bv = *(const float4*)&W1[(k0 + b_k) * H_ + n0 + b_n];
        __syncthreads();
        As[(a_k + 0) * 64 + a_m] = av.x;
        As[(a_k + 1) * 64 + a_m] = av.y;
        As[(a_k + 2) * 64 + a_m] = av.z;
        As[(a_k + 3) * 64 + a_m] = av.w;
        *(float4*)&Bs[b_k * 64 + b_n] = bv;
        __syncthreads();
#pragma unroll
        for (int kk = 0; kk < 16; kk++) {
            float4 ra = *(const float4*)&As[kk * 64 + ty * 4];
            float4 rb = *(const float4*)&Bs[kk * 64 + tx * 4];
            acc[0][0] += ra.x * rb.x; acc[0][1] += ra.x * rb.y;
            acc[0][2] += ra.x * rb.z; acc[0][3] += ra.x * rb.w;
            acc[1][0] += ra.y * rb.x; acc[1][1] += ra.y * rb.y;
            acc[1][2] += ra.y * rb.z; acc[1][3] += ra.y * rb.w;
            acc[2][0] += ra.z * rb.x; acc[2][1] += ra.z * rb.y;
            acc[2][2] += ra.z * rb.z; acc[2][3] += ra.z * rb.w;
            acc[3][0] += ra.w * rb.x; acc[3][1] += ra.w * rb.y;
            acc[3][2] += ra.w * rb.z; acc[3][3] += ra.w * rb.w;
        }
    }

    const int jbase = n0 + tx * 4;
    float4 bias = *(const float4*)&b1[jbase];
#pragma unroll
    for (int i = 0; i < 4; i++) {
        int m = m0 + ty * 4 + i;
        int bb = m >> 9;   // m / T
        int tt = m & 511;  // m % T
        float4 o;
        o.x = acc[i][0] + bias.x;
        o.y = acc[i][1] + bias.y;
        o.z = acc[i][2] + bias.z;
        o.w = acc[i][3] + bias.w;
        *(float4*)&g_A[tt * BH_ + bb * H_ + jbase] = o;
    }
}

// ---------------------------------------------------------------------------
// Persistent recurrence: 128 CTAs, CTA owns 4 j-columns (W1h slice in SMEM
// for all steps). Per step: stage h_t in 128-k chunks (register prefetch),
// compute h_{t+1}[b][j] = sigmoid(A[t][b][j] + h_t[b][:] . W1h[:,j]),
// then a grid barrier on monotone per-step counters.
// ---------------------------------------------------------------------------
__global__ __launch_bounds__(256, 1) void recurrence_kernel(
    const float* __restrict__ W1, float* __restrict__ hid_out) {
    __shared__ __align__(16) float Ws[4 * 512];   // [jj][k]
    __shared__ __align__(16) float sh[64 * 132];  // h chunk [b][kk], pitch 132

    const int tid = threadIdx.x;
    const int j0 = blockIdx.x * 4;

    // Load W1h slice once: Ws[jj][k] = W1[(E+k)][j0+jj]
    for (int idx = tid; idx < 4 * 512; idx += 256) {
        int jj = idx >> 9;
        int k = idx & 511;
        Ws[jj * 512 + k] = W1[(E_ + k) * H_ + j0 + jj];
    }

    const int b = tid & 63;
    const int jj = tid >> 6;
    const int j = j0 + jj;

    int lb[8], lk[8];
#pragma unroll
    for (int i = 0; i < 8; i++) {
        int f4 = tid + i * 256;   // 0..2047 float4 slots of a 64x128 chunk
        lb[i] = f4 >> 5;          // row b
        lk[i] = (f4 & 31) * 4;    // col within chunk
    }
    __syncthreads();

    for (int t = 0; t < T_; t++) {
        const float* hprev = g_Hall + t * BH_;
        float acc0 = 0.f, acc1 = 0.f, acc2 = 0.f, acc3 = 0.f;

        float4 pf[8];
#pragma unroll
        for (int i = 0; i < 8; i++)
            pf[i] = *(const float4*)&hprev[lb[i] * H_ + lk[i]];

        for (int k0 = 0; k0 < H_; k0 += 128) {
            __syncthreads();
#pragma unroll
            for (int i = 0; i < 8; i++) {
                float* d = &sh[lb[i] * 132 + lk[i]];
                d[0] = pf[i].x; d[1] = pf[i].y; d[2] = pf[i].z; d[3] = pf[i].w;
            }
            __syncthreads();
            if (k0 + 128 < H_) {
#pragma unroll
                for (int i = 0; i < 8; i++)
                    pf[i] = *(const float4*)&hprev[lb[i] * H_ + (k0 + 128) + lk[i]];
            }
            const float* hrow = &sh[b * 132];
            const float* wrow = &Ws[jj * 512 + k0];
#pragma unroll
            for (int kk = 0; kk < 128; kk += 4) {
                float4 hv = *(const float4*)&hrow[kk];
                float4 wv = *(const float4*)&wrow[kk];
                acc0 += hv.x * wv.x;
                acc1 += hv.y * wv.y;
                acc2 += hv.z * wv.z;
                acc3 += hv.w * wv.w;
            }
        }

        float a = g_A[t * BH_ + b * H_ + j] + ((acc0 + acc1) + (acc2 + acc3));
        float hnew = 1.0f / (1.0f + __expf(-a));
        g_Hall[(t + 1) * BH_ + b * H_ + j] = hnew;
        if (hid_out != nullptr && t == T_ - 1) hid_out[b * H_ + j] = hnew;

        // grid barrier for step t
        __threadfence();   // release stores + CCTL.IVALL (L1 invalidate)
        __syncthreads();
        if (tid == 0) {
            atomicAdd(&g_cnt[t], 1u);
            while (*((volatile unsigned int*)&g_cnt[t]) < (unsigned)GREC) {}
        }
        __syncthreads();
    }
}

// ---------------------------------------------------------------------------
// Post-GEMM: out[b,t,j] = b2[j] + x[b,t,:]@W2x[:,j] + h_t[b,:]@W2h[:,j]
// K = 1024 (first 512 from X, last 512 from g_Hall). Output row m = b*T+t
// matches d_out layout [B,T,O] directly.
// ---------------------------------------------------------------------------
__global__ __launch_bounds__(256) void gemm_post_kernel(
    const float* __restrict__ X, const float* __restrict__ W2,
    const float* __restrict__ b2, float* __restrict__ out) {
    __shared__ __align__(16) float As[16 * 64];
    __shared__ __align__(16) float Bs[16 * 64];
    const int tid = threadIdx.x;
    const int m0 = blockIdx.y * 64;
    const int n0 = blockIdx.x * 64;
    const int tx = tid & 15;
    const int ty = tid >> 4;
    const int a_m = tid >> 2;
    const int a_k = (tid & 3) * 4;
    const int b_k = tid >> 4;
    const int b_n = (tid & 15) * 4;

    const int m_ld = m0 + a_m;
    const int tt_ld = m_ld & 511;
    const int bb_ld = m_ld >> 9;

    float acc[4][4];
#pragma unroll
    for (int i = 0; i < 4; i++)
#pragma unroll
        for (int j = 0; j < 4; j++) acc[i][j] = 0.0f;

    for (int k0 = 0; k0 < E_ + H_; k0 += 16) {
        float4 av;
        if (k0 < E_) {
            av = *(const float4*)&X[m_ld * E_ + k0 + a_k];
        } else {
            av = *(const float4*)&g_Hall[tt_ld * BH_ + bb_ld * H_ + (k0 - E_) + a_k];
        }
        float4 bv = *(const float4*)&W2[(k0 + b_k) * O_ + n0 + b_n];
        __syncthreads();
        As[(a_k + 0) * 64 + a_m] = av.x;
        As[(a_k + 1) * 64 + a_m] = av.y;
        As[(a_k + 2) * 64 + a_m] = av.z;
        As[(a_k + 3) * 64 + a_m] = av.w;
        *(float4*)&Bs[b_k * 64 + b_n] = bv;
        __syncthreads();
#pragma unroll
        for (int kk = 0; kk < 16; kk++) {
            float4 ra = *(const float4*)&As[kk * 64 + ty * 4];
            float4 rb = *(const float4*)&Bs[kk * 64 + tx * 4];
            acc[0][0] += ra.x * rb.x; acc[0][1] += ra.x * rb.y;
            acc[0][2] += ra.x * rb.z; acc[0][3] += ra.x * rb.w;
            acc[1][0] += ra.y * rb.x; acc[1][1] += ra.y * rb.y;
            acc[1][2] += ra.y * rb.z; acc[1][3] += ra.y * rb.w;
            acc[2][0] += ra.z * rb.x; acc[2][1] += ra.z * rb.y;
            acc[2][2] += ra.z * rb.z; acc[2][3] += ra.z * rb.w;
            acc[3][0] += ra.w * rb.x; acc[3][1] += ra.w * rb.y;
            acc[3][2] += ra.w * rb.z; acc[3][3] += ra.w * rb.w;
        }
    }

    const int jbase = n0 + tx * 4;
    float4 bias = *(const float4*)&b2[jbase];
#pragma unroll
    for (int i = 0; i < 4; i++) {
        int m = m0 + ty * 4 + i;
        float4 o;
        o.x = acc[i][0] + bias.x;
        o.y = acc[i][1] + bias.y;
        o.z = acc[i][2] + bias.z;
        o.w = acc[i][3] + bias.w;
        *(float4*)&out[m * O_ + jbase] = o;
    }
}

// ---------------------------------------------------------------------------
extern "C" void kernel_launch(void* const* d_in, const int* in_sizes, int n_in,
                              void* d_out, int out_size) {
    const float* x = (const float*)d_in[0];
    const float* W1 = (const float*)d_in[1];
    const float* b1 = (const float*)d_in[2];
    const float* W2 = (const float*)d_in[3];
    const float* b2 = (const float*)d_in[4];
    float* out = (float*)d_out;

    float* hid_out = nullptr;
    if (out_size >= B_ * T_ * O_ + B_ * H_)
        hid_out = out + (size_t)B_ * T_ * O_;

    init_kernel<<<128, 256>>>();
    gemm_pre_kernel<<<dim3(H_ / 64, (B_ * T_) / 64), 256>>>(x, W1, b1);
    recurrence_kernel<<<GREC, 256>>>(W1, hid_out);
    gemm_post_kernel<<<dim3(O_ / 64, (B_ * T_) / 64), 256>>>(x, W2, b2, out);
}

// round 5
// speedup vs baseline: 1.4792x; 1.4784x over previous
#include <cuda_runtime.h>
#include <cuda_bf16.h>
#include <cstdint>

#define B_ 64
#define T_ 512
#define E_ 512
#define H_ 512
#define O_ 512
#define BH_ (B_ * H_)
#define NREC 16

// Scratch (device globals — no runtime allocation allowed)
__device__ float g_A[(size_t)T_ * BH_];                  // [t][b][j]  x@W1x + b1
__device__ float g_Hall[(size_t)(T_ + 1) * BH_];         // [t][b][k]  hidden fp32
__device__ __nv_bfloat16 g_Hb[(size_t)(T_ + 1) * BH_];   // [t][b][k]  hidden bf16
__device__ unsigned int g_cnt[T_];                       // per-step barrier counters

#define HS_STRIDE 520  // halfs per row (1040 B): conflict-free ldmatrix phases

__device__ __forceinline__ uint32_t smem_u32(const void* p) {
    uint32_t a;
    asm("{ .reg .u64 t; cvta.to.shared.u64 t, %1; cvt.u32.u64 %0, t; }"
        : "=r"(a) : "l"(p));
    return a;
}
__device__ __forceinline__ void cp16(uint32_t dst, const void* src) {
    asm volatile("cp.async.cg.shared.global [%0], [%1], 16;" :: "r"(dst), "l"(src));
}
__device__ __forceinline__ void ldmatrix_x4(uint32_t& a0, uint32_t& a1,
                                            uint32_t& a2, uint32_t& a3,
                                            uint32_t addr) {
    asm volatile("ldmatrix.sync.aligned.m8n8.x4.shared.b16 {%0,%1,%2,%3}, [%4];"
                 : "=r"(a0), "=r"(a1), "=r"(a2), "=r"(a3) : "r"(addr));
}
__device__ __forceinline__ void mma16816(float& c0, float& c1, float& c2, float& c3,
                                         uint32_t a0, uint32_t a1, uint32_t a2,
                                         uint32_t a3, uint32_t b0, uint32_t b1) {
    asm volatile(
        "mma.sync.aligned.m16n8k16.row.col.f32.bf16.bf16.f32 "
        "{%0,%1,%2,%3}, {%4,%5,%6,%7}, {%8,%9}, {%0,%1,%2,%3};"
        : "+f"(c0), "+f"(c1), "+f"(c2), "+f"(c3)
        : "r"(a0), "r"(a1), "r"(a2), "r"(a3), "r"(b0), "r"(b1));
}
__device__ __forceinline__ uint32_t packbf2(float lo, float hi) {
    __nv_bfloat162 p = __floats2bfloat162_rn(lo, hi);
    return *(uint32_t*)&p;
}

// ---------------------------------------------------------------------------
// Init: zero step counters, h_0 (fp32 + bf16) — every replay, determinism
// ---------------------------------------------------------------------------
__global__ void init_kernel() {
    int i = blockIdx.x * blockDim.x + threadIdx.x;  // 32768 threads
    if (i < T_) g_cnt[i] = 0u;
    if (i < BH_) g_Hall[i] = 0.0f;
    if (i < BH_ / 2) ((uint32_t*)g_Hb)[i] = 0u;
}

// ---------------------------------------------------------------------------
// Pre-GEMM (SIMT fp32): A[t][b][j] = x[b,t,:]@W1x[:,j] + b1[j]
// ---------------------------------------------------------------------------
__global__ __launch_bounds__(256) void gemm_pre_kernel(
    const float* __restrict__ X, const float* __restrict__ W1,
    const float* __restrict__ b1) {
    __shared__ __align__(16) float As[16 * 64];
    __shared__ __align__(16) float Bs[16 * 64];
    const int tid = threadIdx.x;
    const int m0 = blockIdx.y * 64;
    const int n0 = blockIdx.x * 64;
    const int tx = tid & 15;
    const int ty = tid >> 4;
    const int a_m = tid >> 2;
    const int a_k = (tid & 3) * 4;
    const int b_k = tid >> 4;
    const int b_n = (tid & 15) * 4;

    float acc[4][4];
#pragma unroll
    for (int i = 0; i < 4; i++)
#pragma unroll
        for (int j = 0; j < 4; j++) acc[i][j] = 0.0f;

    for (int k0 = 0; k0 < E_; k0 += 16) {
        float4 av = *(const float4*)&X[(m0 + a_m) * E_ + k0 + a_k];
        float4 bv = *(const float4*)&W1[(k0 + b_k) * H_ + n0 + b_n];
        __syncthreads();
        As[(a_k + 0) * 64 + a_m] = av.x;
        As[(a_k + 1) * 64 + a_m] = av.y;
        As[(a_k + 2) * 64 + a_m] = av.z;
        As[(a_k + 3) * 64 + a_m] = av.w;
        *(float4*)&Bs[b_k * 64 + b_n] = bv;
        __syncthreads();
#pragma unroll
        for (int kk = 0; kk < 16; kk++) {
            float4 ra = *(const float4*)&As[kk * 64 + ty * 4];
            float4 rb = *(const float4*)&Bs[kk * 64 + tx * 4];
            acc[0][0] += ra.x * rb.x; acc[0][1] += ra.x * rb.y;
            acc[0][2] += ra.x * rb.z; acc[0][3] += ra.x * rb.w;
            acc[1][0] += ra.y * rb.x; acc[1][1] += ra.y * rb.y;
            acc[1][2] += ra.y * rb.z; acc[1][3] += ra.y * rb.w;
            acc[2][0] += ra.z * rb.x; acc[2][1] += ra.z * rb.y;
            acc[2][2] += ra.z * rb.z; acc[2][3] += ra.z * rb.w;
            acc[3][0] += ra.w * rb.x; acc[3][1] += ra.w * rb.y;
            acc[3][2] += ra.w * rb.z; acc[3][3] += ra.w * rb.w;
        }
    }

    const int jbase = n0 + tx * 4;
    float4 bias = *(const float4*)&b1[jbase];
#pragma unroll
    for (int i = 0; i < 4; i++) {
        int m = m0 + ty * 4 + i;
        int bb = m >> 9;
        int tt = m & 511;
        float4 o;
        o.x = acc[i][0] + bias.x;
        o.y = acc[i][1] + bias.y;
        o.z = acc[i][2] + bias.z;
        o.w = acc[i][3] + bias.w;
        *(float4*)&g_A[(size_t)tt * BH_ + bb * H_ + jbase] = o;
    }
}

// ---------------------------------------------------------------------------
// Persistent HMMA recurrence. 16 CTAs x 256 threads, CTA owns 32 j-cols.
// W1h slice lives in REGISTERS (128 regs/thread) for all 512 steps.
// Per step: cp.async h_t (bf16) -> ldmatrix A frags -> mma.sync -> epilogue.
// ---------------------------------------------------------------------------
__global__ __launch_bounds__(256, 1) void recurrence_mma(
    const float* __restrict__ W1, float* __restrict__ hid_out) {
    extern __shared__ __align__(16) char dyn[];  // hs: 64 rows x 520 halfs

    const int tid = threadIdx.x;
    const int wid = tid >> 5;
    const int lane = tid & 31;
    const int j0 = blockIdx.x * 32;
    const int m0w = (wid >> 1) * 16;   // warp's b-row base
    const int n0w = (wid & 1) * 16;    // warp's j base within slice
    const int g = lane >> 2;           // group id
    const int t4 = lane & 3;

    const uint32_t hs = smem_u32(dyn);

    // ---- preload B fragments (W1h^T slice) into registers, once ----
    const float* Wh = W1 + (size_t)E_ * H_;  // [k][j]
    uint32_t bfrag[32][2][2];
    {
        const int nb = j0 + n0w + g;
#pragma unroll
        for (int s = 0; s < 32; s++) {
#pragma unroll
            for (int nt = 0; nt < 2; nt++) {
                const int n = nb + nt * 8;
                const int k0 = 16 * s + 2 * t4;
                float f00 = Wh[(size_t)k0 * H_ + n];
                float f01 = Wh[(size_t)(k0 + 1) * H_ + n];
                float f10 = Wh[(size_t)(k0 + 8) * H_ + n];
                float f11 = Wh[(size_t)(k0 + 9) * H_ + n];
                bfrag[s][nt][0] = packbf2(f00, f01);
                bfrag[s][nt][1] = packbf2(f10, f11);
            }
        }
    }

    // per-lane ldmatrix base address (row = m0w + (lane&7) + ((lane>>3)&1)*8,
    // k-half select = (lane>>4)*8 halfs = (lane>>4)*16 bytes)
    const int lrow = m0w + (lane & 7) + ((lane >> 3) & 1) * 8;
    const uint32_t lm_base = hs + (uint32_t)lrow * (HS_STRIDE * 2) + (lane >> 4) * 16;

    // cp.async fill pattern: 4096 16B chunks, 16 per thread
    const int c_row[16] = {0};  // placeholder to keep compiler happy (unused)
    (void)c_row;

    for (int t = 0; t < T_; t++) {
        // ---- stage h_t bf16 into SMEM (padded stride) ----
        const char* hsrc = (const char*)(g_Hb + (size_t)t * BH_);
#pragma unroll
        for (int c = tid; c < 4096; c += 256) {
            int row = c >> 6;
            int ck = c & 63;  // 16B chunk within row
            cp16(hs + (uint32_t)row * (HS_STRIDE * 2) + ck * 16,
                 hsrc + row * 1024 + ck * 16);
        }
        asm volatile("cp.async.commit_group;" ::: "memory");
        asm volatile("cp.async.wait_group 0;" ::: "memory");
        __syncthreads();

        // ---- 64x32 = (16x16 per warp) MMA over K=512 ----
        float c0[4] = {0.f, 0.f, 0.f, 0.f};
        float c1[4] = {0.f, 0.f, 0.f, 0.f};
#pragma unroll
        for (int s = 0; s < 32; s++) {
            uint32_t a0, a1, a2, a3;
            ldmatrix_x4(a0, a1, a2, a3, lm_base + s * 32);
            mma16816(c0[0], c0[1], c0[2], c0[3], a0, a1, a2, a3,
                     bfrag[s][0][0], bfrag[s][0][1]);
            mma16816(c1[0], c1[1], c1[2], c1[3], a0, a1, a2, a3,
                     bfrag[s][1][0], bfrag[s][1][1]);
        }

        // ---- epilogue: add g_A, sigmoid, store fp32 + bf16 ----
        {
            const int r0 = m0w + g;
            const int r1 = r0 + 8;
            const size_t baseA = (size_t)t * BH_;
            const size_t baseH = (size_t)(t + 1) * BH_;
#pragma unroll
            for (int nt = 0; nt < 2; nt++) {
                const int j = j0 + n0w + nt * 8 + 2 * t4;
                const float* cc = nt == 0 ? c0 : c1;
                float2 av0 = *(const float2*)&g_A[baseA + (size_t)r0 * H_ + j];
                float2 av1 = *(const float2*)&g_A[baseA + (size_t)r1 * H_ + j];
                float2 o0, o1;
                o0.x = 1.0f / (1.0f + __expf(-(av0.x + cc[0])));
                o0.y = 1.0f / (1.0f + __expf(-(av0.y + cc[1])));
                o1.x = 1.0f / (1.0f + __expf(-(av1.x + cc[2])));
                o1.y = 1.0f / (1.0f + __expf(-(av1.y + cc[3])));
                *(float2*)&g_Hall[baseH + (size_t)r0 * H_ + j] = o0;
                *(float2*)&g_Hall[baseH + (size_t)r1 * H_ + j] = o1;
                *(uint32_t*)&g_Hb[baseH + (size_t)r0 * H_ + j] = packbf2(o0.x, o0.y);
                *(uint32_t*)&g_Hb[baseH + (size_t)r1 * H_ + j] = packbf2(o1.x, o1.y);
                if (hid_out != nullptr && t == T_ - 1) {
                    *(float2*)&hid_out[r0 * H_ + j] = o0;
                    *(float2*)&hid_out[r1 * H_ + j] = o1;
                }
            }
        }

        // ---- grid barrier (publish h_{t+1}, then counter) ----
        if (t < T_ - 1) {
            __threadfence();
            __syncthreads();
            if (tid == 0) {
                atomicAdd(&g_cnt[t], 1u);
                while (*((volatile unsigned int*)&g_cnt[t]) < (unsigned)NREC) {}
            }
            __syncthreads();
        }
    }
}

// ---------------------------------------------------------------------------
// Post-GEMM (SIMT fp32): out[b,t,j] = b2[j] + x@W2x + h_t@W2h   (K = 1024)
// ---------------------------------------------------------------------------
__global__ __launch_bounds__(256) void gemm_post_kernel(
    const float* __restrict__ X, const float* __restrict__ W2,
    const float* __restrict__ b2, float* __restrict__ out) {
    __shared__ __align__(16) float As[16 * 64];
    __shared__ __align__(16) float Bs[16 * 64];
    const int tid = threadIdx.x;
    const int m0 = blockIdx.y * 64;
    const int n0 = blockIdx.x * 64;
    const int tx = tid & 15;
    const int ty = tid >> 4;
    const int a_m = tid >> 2;
    const int a_k = (tid & 3) * 4;
    const int b_k = tid >> 4;
    const int b_n = (tid & 15) * 4;

    const int m_ld = m0 + a_m;
    const int tt_ld = m_ld & 511;
    const int bb_ld = m_ld >> 9;

    float acc[4][4];
#pragma unroll
    for (int i = 0; i < 4; i++)
#pragma unroll
        for (int j = 0; j < 4; j++) acc[i][j] = 0.0f;

    for (int k0 = 0; k0 < E_ + H_; k0 += 16) {
        float4 av;
        if (k0 < E_) {
            av = *(const float4*)&X[m_ld * E_ + k0 + a_k];
        } else {
            av = *(const float4*)&g_Hall[(size_t)tt_ld * BH_ + bb_ld * H_ + (k0 - E_) + a_k];
        }
        float4 bv = *(const float4*)&W2[(k0 + b_k) * O_ + n0 + b_n];
        __syncthreads();
        As[(a_k + 0) * 64 + a_m] = av.x;
        As[(a_k + 1) * 64 + a_m] = av.y;
        As[(a_k + 2) * 64 + a_m] = av.z;
        As[(a_k + 3) * 64 + a_m] = av.w;
        *(float4*)&Bs[b_k * 64 + b_n] = bv;
        __syncthreads();
#pragma unroll
        for (int kk = 0; kk < 16; kk++) {
            float4 ra = *(const float4*)&As[kk * 64 + ty * 4];
            float4 rb = *(const float4*)&Bs[kk * 64 + tx * 4];
            acc[0][0] += ra.x * rb.x; acc[0][1] += ra.x * rb.y;
            acc[0][2] += ra.x * rb.z; acc[0][3] += ra.x * rb.w;
            acc[1][0] += ra.y * rb.x; acc[1][1] += ra.y * rb.y;
            acc[1][2] += ra.y * rb.z; acc[1][3] += ra.y * rb.w;
            acc[2][0] += ra.z * rb.x; acc[2][1] += ra.z * rb.y;
            acc[2][2] += ra.z * rb.z; acc[2][3] += ra.z * rb.w;
            acc[3][0] += ra.w * rb.x; acc[3][1] += ra.w * rb.y;
            acc[3][2] += ra.w * rb.z; acc[3][3] += ra.w * rb.w;
        }
    }

    const int jbase = n0 + tx * 4;
    float4 bias = *(const float4*)&b2[jbase];
#pragma unroll
    for (int i = 0; i < 4; i++) {
        int m = m0 + ty * 4 + i;
        float4 o;
        o.x = acc[i][0] + bias.x;
        o.y = acc[i][1] + bias.y;
        o.z = acc[i][2] + bias.z;
        o.w = acc[i][3] + bias.w;
        *(float4*)&out[m * O_ + jbase] = o;
    }
}

// ---------------------------------------------------------------------------
extern "C" void kernel_launch(void* const* d_in, const int* in_sizes, int n_in,
                              void* d_out, int out_size) {
    const float* x = (const float*)d_in[0];
    const float* W1 = (const float*)d_in[1];
    const float* b1 = (const float*)d_in[2];
    const float* W2 = (const float*)d_in[3];
    const float* b2 = (const float*)d_in[4];
    float* out = (float*)d_out;

    float* hid_out = nullptr;
    if (out_size >= B_ * T_ * O_ + B_ * H_)
        hid_out = out + (size_t)B_ * T_ * O_;

    const int dyn_smem = 64 * HS_STRIDE * 2 + 256;  // 66816 B
    cudaFuncSetAttribute(recurrence_mma,
                         cudaFuncAttributeMaxDynamicSharedMemorySize, dyn_smem);

    init_kernel<<<128, 256>>>();
    gemm_pre_kernel<<<dim3(H_ / 64, (B_ * T_) / 64), 256>>>(x, W1, b1);
    recurrence_mma<<<NREC, 256, dyn_smem>>>(W1, hid_out);
    gemm_post_kernel<<<dim3(O_ / 64, (B_ * T_) / 64), 256>>>(x, W2, b2, out);
}

// round 6
// speedup vs baseline: 1.7903x; 1.2103x over previous
#include <cuda_runtime.h>
#include <cuda_bf16.h>
#include <cstdint>

#define B_ 64
#define T_ 512
#define E_ 512
#define H_ 512
#define O_ 512
#define BH_ (B_ * H_)
#define HSTR 520  // halfs per h row (1040 B): conflict-free ldmatrix phases

// Scratch (device globals — no runtime allocation allowed)
__device__ float g_A[(size_t)T_ * BH_];           // [t][b][j]  x@W1x + b1
__device__ float g_Hall[(size_t)(T_ + 1) * BH_];  // [t][b][k]  hidden fp32

__device__ __forceinline__ uint32_t smem_u32(const void* p) {
    uint32_t a;
    asm("{ .reg .u64 t; cvta.to.shared.u64 t, %1; cvt.u32.u64 %0, t; }"
        : "=r"(a) : "l"(p));
    return a;
}
__device__ __forceinline__ void ldmatrix_x4(uint32_t& a0, uint32_t& a1,
                                            uint32_t& a2, uint32_t& a3,
                                            uint32_t addr) {
    asm volatile("ldmatrix.sync.aligned.m8n8.x4.shared.b16 {%0,%1,%2,%3}, [%4];"
                 : "=r"(a0), "=r"(a1), "=r"(a2), "=r"(a3) : "r"(addr));
}
__device__ __forceinline__ void mma16816(float& c0, float& c1, float& c2, float& c3,
                                         uint32_t a0, uint32_t a1, uint32_t a2,
                                         uint32_t a3, uint32_t b0, uint32_t b1) {
    asm volatile(
        "mma.sync.aligned.m16n8k16.row.col.f32.bf16.bf16.f32 "
        "{%0,%1,%2,%3}, {%4,%5,%6,%7}, {%8,%9}, {%0,%1,%2,%3};"
        : "+f"(c0), "+f"(c1), "+f"(c2), "+f"(c3)
        : "r"(a0), "r"(a1), "r"(a2), "r"(a3), "r"(b0), "r"(b1));
}
__device__ __forceinline__ uint32_t packbf2(float lo, float hi) {
    __nv_bfloat162 p = __floats2bfloat162_rn(lo, hi);
    return *(uint32_t*)&p;
}
__device__ __forceinline__ uint32_t mapa_u32(uint32_t addr, uint32_t rank) {
    uint32_t r;
    asm("mapa.shared::cluster.u32 %0, %1, %2;" : "=r"(r) : "r"(addr), "r"(rank));
    return r;
}
__device__ __forceinline__ void st_cluster_u32(uint32_t addr, uint32_t v) {
    asm volatile("st.shared::cluster.u32 [%0], %1;" :: "r"(addr), "r"(v) : "memory");
}
#define CLUSTER_SYNC() do {                                             \
    asm volatile("barrier.cluster.arrive.aligned;" ::: "memory");       \
    asm volatile("barrier.cluster.wait.aligned;" ::: "memory");         \
} while (0)

__device__ __forceinline__ float sigmoidf_(float x) {
    return 1.0f / (1.0f + __expf(-x));
}

// ---------------------------------------------------------------------------
// Init: zero h_0 slab of g_Hall (every replay — determinism)
// ---------------------------------------------------------------------------
__global__ void init_kernel() {
    int i = blockIdx.x * blockDim.x + threadIdx.x;
    if (i < BH_) g_Hall[i] = 0.0f;
}

// ---------------------------------------------------------------------------
// Pre-GEMM (SIMT fp32): A[t][b][j] = x[b,t,:]@W1x[:,j] + b1[j]
// ---------------------------------------------------------------------------
__global__ __launch_bounds__(256) void gemm_pre_kernel(
    const float* __restrict__ X, const float* __restrict__ W1,
    const float* __restrict__ b1) {
    __shared__ __align__(16) float As[16 * 64];
    __shared__ __align__(16) float Bs[16 * 64];
    const int tid = threadIdx.x;
    const int m0 = blockIdx.y * 64;
    const int n0 = blockIdx.x * 64;
    const int tx = tid & 15;
    const int ty = tid >> 4;
    const int a_m = tid >> 2;
    const int a_k = (tid & 3) * 4;
    const int b_k = tid >> 4;
    const int b_n = (tid & 15) * 4;

    float acc[4][4];
#pragma unroll
    for (int i = 0; i < 4; i++)
#pragma unroll
        for (int j = 0; j < 4; j++) acc[i][j] = 0.0f;

    for (int k0 = 0; k0 < E_; k0 += 16) {
        float4 av = *(const float4*)&X[(m0 + a_m) * E_ + k0 + a_k];
        float4 bv = *(const float4*)&W1[(k0 + b_k) * H_ + n0 + b_n];
        __syncthreads();
        As[(a_k + 0) * 64 + a_m] = av.x;
        As[(a_k + 1) * 64 + a_m] = av.y;
        As[(a_k + 2) * 64 + a_m] = av.z;
        As[(a_k + 3) * 64 + a_m] = av.w;
        *(float4*)&Bs[b_k * 64 + b_n] = bv;
        __syncthreads();
#pragma unroll
        for (int kk = 0; kk < 16; kk++) {
            float4 ra = *(const float4*)&As[kk * 64 + ty * 4];
            float4 rb = *(const float4*)&Bs[kk * 64 + tx * 4];
            acc[0][0] += ra.x * rb.x; acc[0][1] += ra.x * rb.y;
            acc[0][2] += ra.x * rb.z; acc[0][3] += ra.x * rb.w;
            acc[1][0] += ra.y * rb.x; acc[1][1] += ra.y * rb.y;
            acc[1][2] += ra.y * rb.z; acc[1][3] += ra.y * rb.w;
            acc[2][0] += ra.z * rb.x; acc[2][1] += ra.z * rb.y;
            acc[2][2] += ra.z * rb.z; acc[2][3] += ra.z * rb.w;
            acc[3][0] += ra.w * rb.x; acc[3][1] += ra.w * rb.y;
            acc[3][2] += ra.w * rb.z; acc[3][3] += ra.w * rb.w;
        }
    }

    const int jbase = n0 + tx * 4;
    float4 bias = *(const float4*)&b1[jbase];
#pragma unroll
    for (int i = 0; i < 4; i++) {
        int m = m0 + ty * 4 + i;
        int bb = m >> 9;
        int tt = m & 511;
        float4 o;
        o.x = acc[i][0] + bias.x;
        o.y = acc[i][1] + bias.y;
        o.z = acc[i][2] + bias.z;
        o.w = acc[i][3] + bias.w;
        *(float4*)&g_A[(size_t)tt * BH_ + bb * H_ + jbase] = o;
    }
}

// ---------------------------------------------------------------------------
// Cluster recurrence: 4 clusters x 4 CTAs. Cluster owns 16 batch rows (M=16);
// CTA owns 128 j-cols with W1h slice in registers. h double-buffered in SMEM,
// exchanged via st.shared::cluster; one barrier.cluster per step. No GMEM h
// round-trip, no GPU-scope fence.
// ---------------------------------------------------------------------------
__global__ __launch_bounds__(256, 1) __cluster_dims__(4, 1, 1)
void recurrence_cluster(const float* __restrict__ W1, float* __restrict__ hid_out) {
    __shared__ __align__(16) uint16_t hsm[2][16 * HSTR];  // 33280 B

    const int tid = threadIdx.x;
    const int wid = tid >> 5;
    const int lane = tid & 31;
    uint32_t crank;
    asm("mov.u32 %0, %%cluster_ctarank;" : "=r"(crank));
    const int bbase = (blockIdx.x >> 2) * 16;  // batch-group base row
    const int g = lane >> 2;
    const int t4 = lane & 3;
    const int n0w = wid * 16;  // warp's j base within the 128-col slice

    // ---- preload W1h^T fragments into registers (once, R5-proven layout) ----
    const float* Wh = W1 + (size_t)E_ * H_;  // [k][j]
    uint32_t bfrag[32][2][2];
    {
        const int nb = (int)crank * 128 + n0w + g;
#pragma unroll
        for (int s = 0; s < 32; s++) {
#pragma unroll
            for (int nt = 0; nt < 2; nt++) {
                const int n = nb + nt * 8;
                const int k0 = 16 * s + 2 * t4;
                float f00 = Wh[(size_t)k0 * H_ + n];
                float f01 = Wh[(size_t)(k0 + 1) * H_ + n];
                float f10 = Wh[(size_t)(k0 + 8) * H_ + n];
                float f11 = Wh[(size_t)(k0 + 9) * H_ + n];
                bfrag[s][nt][0] = packbf2(f00, f01);
                bfrag[s][nt][1] = packbf2(f10, f11);
            }
        }
    }

    // ---- zero both h buffers (h_0 = 0) ----
    for (int i = tid; i < (int)(2 * 16 * HSTR * 2 / 16); i += 256)
        ((uint4*)hsm)[i] = make_uint4(0u, 0u, 0u, 0u);
    __syncthreads();
    CLUSTER_SYNC();  // peers' zeroing visible before any remote writes

    const uint32_t hb0 = smem_u32(&hsm[0][0]);
    const uint32_t hb1 = smem_u32(&hsm[1][0]);
    uint32_t rb[4][2];
#pragma unroll
    for (int r = 0; r < 4; r++) {
        rb[r][0] = mapa_u32(hb0, (uint32_t)r);
        rb[r][1] = mapa_u32(hb1, (uint32_t)r);
    }

    const int lrow = (lane & 7) + ((lane >> 3) & 1) * 8;
    const uint32_t lmoff = (uint32_t)lrow * (HSTR * 2) + (lane >> 4) * 16;
    const uint32_t lm0 = hb0 + lmoff;
    const uint32_t lm1 = hb1 + lmoff;

    // epilogue/ prefetch column indices
    const int jg0 = (int)crank * 128 + n0w + 2 * t4;      // nt=0 column pair
    const int jg1 = jg0 + 8;                              // nt=1 column pair
    const int br0 = bbase + g;
    const int br1 = br0 + 8;

    for (int t = 0; t < T_; t++) {
        // ---- prefetch g_A[t] into registers (h-independent, hides DRAM) ----
        const size_t baseA = (size_t)t * BH_;
        float2 pa00 = *(const float2*)&g_A[baseA + (size_t)br0 * H_ + jg0];
        float2 pa01 = *(const float2*)&g_A[baseA + (size_t)br1 * H_ + jg0];
        float2 pa10 = *(const float2*)&g_A[baseA + (size_t)br0 * H_ + jg1];
        float2 pa11 = *(const float2*)&g_A[baseA + (size_t)br1 * H_ + jg1];

        // ---- mma over K=512 from own h buffer ----
        const uint32_t lm = (t & 1) ? lm1 : lm0;
        float c0[4] = {0.f, 0.f, 0.f, 0.f};
        float c1[4] = {0.f, 0.f, 0.f, 0.f};
#pragma unroll
        for (int s = 0; s < 32; s++) {
            uint32_t a0, a1, a2, a3;
            ldmatrix_x4(a0, a1, a2, a3, lm + s * 32);
            mma16816(c0[0], c0[1], c0[2], c0[3], a0, a1, a2, a3,
                     bfrag[s][0][0], bfrag[s][0][1]);
            mma16816(c1[0], c1[1], c1[2], c1[3], a0, a1, a2, a3,
                     bfrag[s][1][0], bfrag[s][1][1]);
        }

        // ---- epilogue: sigmoid, store fp32 h, push bf16 h to cluster ----
        const size_t baseH = (size_t)(t + 1) * BH_;
        float2 o00, o01, o10, o11;
        o00.x = sigmoidf_(pa00.x + c0[0]);
        o00.y = sigmoidf_(pa00.y + c0[1]);
        o01.x = sigmoidf_(pa01.x + c0[2]);
        o01.y = sigmoidf_(pa01.y + c0[3]);
        o10.x = sigmoidf_(pa10.x + c1[0]);
        o10.y = sigmoidf_(pa10.y + c1[1]);
        o11.x = sigmoidf_(pa11.x + c1[2]);
        o11.y = sigmoidf_(pa11.y + c1[3]);

        *(float2*)&g_Hall[baseH + (size_t)br0 * H_ + jg0] = o00;
        *(float2*)&g_Hall[baseH + (size_t)br1 * H_ + jg0] = o01;
        *(float2*)&g_Hall[baseH + (size_t)br0 * H_ + jg1] = o10;
        *(float2*)&g_Hall[baseH + (size_t)br1 * H_ + jg1] = o11;
        if (hid_out != nullptr && t == T_ - 1) {
            *(float2*)&hid_out[br0 * H_ + jg0] = o00;
            *(float2*)&hid_out[br1 * H_ + jg0] = o01;
            *(float2*)&hid_out[br0 * H_ + jg1] = o10;
            *(float2*)&hid_out[br1 * H_ + jg1] = o11;
        }

        if (t < T_ - 1) {
            const int wb = 1 - (t & 1);
            const uint32_t u00 = packbf2(o00.x, o00.y);
            const uint32_t u01 = packbf2(o01.x, o01.y);
            const uint32_t u10 = packbf2(o10.x, o10.y);
            const uint32_t u11 = packbf2(o11.x, o11.y);
            const uint32_t f00 = (uint32_t)g * (HSTR * 2) + (uint32_t)jg0 * 2;
            const uint32_t f01 = (uint32_t)(g + 8) * (HSTR * 2) + (uint32_t)jg0 * 2;
            const uint32_t f10 = (uint32_t)g * (HSTR * 2) + (uint32_t)jg1 * 2;
            const uint32_t f11 = (uint32_t)(g + 8) * (HSTR * 2) + (uint32_t)jg1 * 2;
#pragma unroll
            for (int r = 0; r < 4; r++) {
                const uint32_t tb = rb[r][wb];
                st_cluster_u32(tb + f00, u00);
                st_cluster_u32(tb + f01, u01);
                st_cluster_u32(tb + f10, u10);
                st_cluster_u32(tb + f11, u11);
            }
            CLUSTER_SYNC();  // release writes / acquire for next step's reads
        }
    }
}

// ---------------------------------------------------------------------------
// Post-GEMM (SIMT fp32): out[b,t,j] = b2[j] + x@W2x + h_t@W2h   (K = 1024)
// ---------------------------------------------------------------------------
__global__ __launch_bounds__(256) void gemm_post_kernel(
    const float* __restrict__ X, const float* __restrict__ W2,
    const float* __restrict__ b2, float* __restrict__ out) {
    __shared__ __align__(16) float As[16 * 64];
    __shared__ __align__(16) float Bs[16 * 64];
    const int tid = threadIdx.x;
    const int m0 = blockIdx.y * 64;
    const int n0 = blockIdx.x * 64;
    const int tx = tid & 15;
    const int ty = tid >> 4;
    const int a_m = tid >> 2;
    const int a_k = (tid & 3) * 4;
    const int b_k = tid >> 4;
    const int b_n = (tid & 15) * 4;

    const int m_ld = m0 + a_m;
    const int tt_ld = m_ld & 511;
    const int bb_ld = m_ld >> 9;

    float acc[4][4];
#pragma unroll
    for (int i = 0; i < 4; i++)
#pragma unroll
        for (int j = 0; j < 4; j++) acc[i][j] = 0.0f;

    for (int k0 = 0; k0 < E_ + H_; k0 += 16) {
        float4 av;
        if (k0 < E_) {
            av = *(const float4*)&X[m_ld * E_ + k0 + a_k];
        } else {
            av = *(const float4*)&g_Hall[(size_t)tt_ld * BH_ + bb_ld * H_ + (k0 - E_) + a_k];
        }
        float4 bv = *(const float4*)&W2[(k0 + b_k) * O_ + n0 + b_n];
        __syncthreads();
        As[(a_k + 0) * 64 + a_m] = av.x;
        As[(a_k + 1) * 64 + a_m] = av.y;
        As[(a_k + 2) * 64 + a_m] = av.z;
        As[(a_k + 3) * 64 + a_m] = av.w;
        *(float4*)&Bs[b_k * 64 + b_n] = bv;
        __syncthreads();
#pragma unroll
        for (int kk = 0; kk < 16; kk++) {
            float4 ra = *(const float4*)&As[kk * 64 + ty * 4];
            float4 rb = *(const float4*)&Bs[kk * 64 + tx * 4];
            acc[0][0] += ra.x * rb.x; acc[0][1] += ra.x * rb.y;
            acc[0][2] += ra.x * rb.z; acc[0][3] += ra.x * rb.w;
            acc[1][0] += ra.y * rb.x; acc[1][1] += ra.y * rb.y;
            acc[1][2] += ra.y * rb.z; acc[1][3] += ra.y * rb.w;
            acc[2][0] += ra.z * rb.x; acc[2][1] += ra.z * rb.y;
            acc[2][2] += ra.z * rb.z; acc[2][3] += ra.z * rb.w;
            acc[3][0] += ra.w * rb.x; acc[3][1] += ra.w * rb.y;
            acc[3][2] += ra.w * rb.z; acc[3][3] += ra.w * rb.w;
        }
    }

    const int jbase = n0 + tx * 4;
    float4 bias = *(const float4*)&b2[jbase];
#pragma unroll
    for (int i = 0; i < 4; i++) {
        int m = m0 + ty * 4 + i;
        float4 o;
        o.x = acc[i][0] + bias.x;
        o.y = acc[i][1] + bias.y;
        o.z = acc[i][2] + bias.z;
        o.w = acc[i][3] + bias.w;
        *(float4*)&out[m * O_ + jbase] = o;
    }
}

// ---------------------------------------------------------------------------
extern "C" void kernel_launch(void* const* d_in, const int* in_sizes, int n_in,
                              void* d_out, int out_size) {
    const float* x = (const float*)d_in[0];
    const float* W1 = (const float*)d_in[1];
    const float* b1 = (const float*)d_in[2];
    const float* W2 = (const float*)d_in[3];
    const float* b2 = (const float*)d_in[4];
    float* out = (float*)d_out;

    float* hid_out = nullptr;
    if (out_size >= B_ * T_ * O_ + B_ * H_)
        hid_out = out + (size_t)B_ * T_ * O_;

    init_kernel<<<128, 256>>>();
    gemm_pre_kernel<<<dim3(H_ / 64, (B_ * T_) / 64), 256>>>(x, W1, b1);
    recurrence_cluster<<<16, 256>>>(W1, hid_out);
    gemm_post_kernel<<<dim3(O_ / 64, (B_ * T_) / 64), 256>>>(x, W2, b2, out);
}